// round 1
// baseline (speedup 1.0000x reference)
#include <cuda_runtime.h>
#include <cuda_bf16.h>
#include <math.h>

#define BB 8
#define NN 2048
#define KK 1024

// ---------------- device state ----------------
__device__ float d_mean0[BB*3], d_mean1[BB*3];
__device__ float d_posesJ[7*12];          // [0]=identity, [1..6]=se3_exp(-dt_j e_j)
__device__ float d_gpose[BB*12];          // current g (3x4)
__device__ float d_igtinv[BB*12];
__device__ float d_estg[BB*12];
__device__ float d_f0[BB*KK], d_fj[BB*6*KK], d_f1[BB*KK];
__device__ float d_J[BB*KK*6];
__device__ float d_Hinv[BB*36];
__device__ float d_r[BB*KK];
__device__ float d_lpart[64];

// ---------------- helpers ----------------
__device__ __forceinline__ void atomicMaxF(float* addr, float val) {
    if (val >= 0.f) atomicMax((int*)addr, __float_as_int(val));
    else            atomicMin((unsigned int*)addr, __float_as_uint(val));
}

// se3_exp (double internals, matches reference formula), output 3x4 row-major float
__device__ void se3_exp_d(const double w[3], const double v[3], float out[12]) {
    double t2 = w[0]*w[0] + w[1]*w[1] + w[2]*w[2];
    double t = sqrt(t2);
    double A, Bc, Cc;
    if (t < 1e-6) {
        A  = 1.0 - t2/6.0;
        Bc = 0.5 - t2/24.0;
        Cc = 1.0/6.0 - t2/120.0;
    } else {
        double st = sin(t), ct = cos(t);
        A  = st / t;
        Bc = (1.0 - ct) / t2;
        Cc = (t - st) / (t2 * t);
    }
    double W[3][3] = {{0.0, -w[2], w[1]}, {w[2], 0.0, -w[0]}, {-w[1], w[0], 0.0}};
    double W2[3][3];
    for (int i = 0; i < 3; i++)
        for (int j = 0; j < 3; j++)
            W2[i][j] = w[i]*w[j] - (i==j ? t2 : 0.0);
    double R[3][3], V[3][3];
    for (int i = 0; i < 3; i++)
        for (int j = 0; j < 3; j++) {
            double I = (i==j) ? 1.0 : 0.0;
            R[i][j] = I + A  * W[i][j] + Bc * W2[i][j];
            V[i][j] = I + Bc * W[i][j] + Cc * W2[i][j];
        }
    for (int i = 0; i < 3; i++) {
        double p = V[i][0]*v[0] + V[i][1]*v[1] + V[i][2]*v[2];
        out[i*4+0] = (float)R[i][0];
        out[i*4+1] = (float)R[i][1];
        out[i*4+2] = (float)R[i][2];
        out[i*4+3] = (float)p;
    }
}

// ---------------- means ----------------
__global__ void means_kernel(const float* __restrict__ p_tgt, const float* __restrict__ p_src) {
    int b = blockIdx.x, tid = threadIdx.x;
    float a[6] = {0,0,0,0,0,0};
    for (int n = tid; n < NN; n += 256) {
        const float* pt = p_tgt + ((size_t)b*NN + n)*3;
        const float* ps = p_src + ((size_t)b*NN + n)*3;
        a[0] += pt[0]; a[1] += pt[1]; a[2] += pt[2];
        a[3] += ps[0]; a[4] += ps[1]; a[5] += ps[2];
    }
    for (int off = 16; off; off >>= 1)
        #pragma unroll
        for (int q = 0; q < 6; q++) a[q] += __shfl_down_sync(0xffffffffu, a[q], off);
    __shared__ float sm[8][6];
    int lane = tid & 31, w = tid >> 5;
    if (lane == 0) { for (int q = 0; q < 6; q++) sm[w][q] = a[q]; }
    __syncthreads();
    if (tid < 6) {
        float s = 0.f;
        for (int w2 = 0; w2 < 8; w2++) s += sm[w2][tid];
        s *= (1.0f / NN);
        if (tid < 3) d_mean0[b*3 + tid] = s;
        else         d_mean1[b*3 + tid - 3] = s;
    }
}

// ---------------- setup: jacobian poses, g=I, igt_inv ----------------
__global__ void setup_kernel(const float* __restrict__ dt, const float* __restrict__ igt_twist) {
    int tid = threadIdx.x;
    if (tid < 7) {
        float out[12];
        if (tid == 0) {
            float I[12] = {1,0,0,0, 0,1,0,0, 0,0,1,0};
            for (int i = 0; i < 12; i++) out[i] = I[i];
        } else {
            int j = tid - 1;
            double w[3] = {0,0,0}, v[3] = {0,0,0};
            double val = -(double)__ldg(&dt[j]);
            if (j < 3) w[j] = val; else v[j-3] = val;
            se3_exp_d(w, v, out);
        }
        for (int i = 0; i < 12; i++) d_posesJ[tid*12 + i] = out[i];
    }
    if (tid >= 8 && tid < 16) {
        int b = tid - 8;
        float I[12] = {1,0,0,0, 0,1,0,0, 0,0,1,0};
        for (int i = 0; i < 12; i++) d_gpose[b*12 + i] = I[i];
    }
    if (tid >= 16 && tid < 24) {
        int b = tid - 16;
        double w[3], v[3];
        for (int i = 0; i < 3; i++) { w[i] = igt_twist[b*6 + i]; v[i] = igt_twist[b*6 + 3 + i]; }
        float g[12];
        se3_exp_d(w, v, g);
        // rigid inverse: R^T, -R^T t
        float inv[12];
        for (int r = 0; r < 3; r++)
            for (int c = 0; c < 3; c++) inv[r*4 + c] = g[c*4 + r];
        for (int r = 0; r < 3; r++)
            inv[r*4 + 3] = -(g[0*4+r]*g[3] + g[1*4+r]*g[7] + g[2*4+r]*g[11]);
        for (int i = 0; i < 12; i++) d_igtinv[b*12 + i] = inv[i];
    }
}

// ---------------- inits ----------------
__global__ void init_f0fj_kernel() {
    int i = blockIdx.x*256 + threadIdx.x;
    if (i < BB*KK) d_f0[i] = -INFINITY;
    else if (i < BB*KK + BB*6*KK) d_fj[i - BB*KK] = -INFINITY;
}
__global__ void init_f1_kernel() {
    int i = blockIdx.x*256 + threadIdx.x;
    if (i < BB*KK) d_f1[i] = -INFINITY;
}

// ---------------- fused encode (pose-transform -> MLP -> max) ----------------
// block: 256 threads, NP=64 points, all 1024 outputs via 16 chunks of 64 cols.
#define OFF_W2  0
#define OFF_H1  8192           /* stride 65, size 64*65=4160 */
#define OFF_W3  0              /* phase B alias over W2+H1, 8192 floats */
#define OFF_H2  12352          /* stride 132, size 64*132=8448 */
#define OFF_RED 20800          /* 16*64 = 1024 */
#define OFF_PTS 21824          /* 64*3 */
#define OFF_W1  22016          /* 192 */
#define OFF_B1  22208          /* 64 */
#define OFF_B2  22272          /* 128 */
#define SMEM_FLOATS 22400
#define SMEM_BYTES (SMEM_FLOATS*4)

template<int MODE>
__global__ __launch_bounds__(256, 2)
void encode_kernel(const float* __restrict__ P,
                   const float* __restrict__ W1g, const float* __restrict__ b1g,
                   const float* __restrict__ W2g, const float* __restrict__ b2g,
                   const float* __restrict__ W3g, const float* __restrict__ b3g) {
    extern __shared__ float sm[];
    int tid = threadIdx.x;

    int b; const float* pose; const float* mean; float* out;
    if (MODE == 0) {
        int bm = blockIdx.y;
        b = bm / 7; int m = bm % 7;
        pose = d_posesJ + m*12;
        mean = d_mean0 + b*3;
        out  = (m == 0) ? (d_f0 + b*KK) : (d_fj + ((size_t)b*6 + (m-1))*KK);
    } else {
        b = blockIdx.y;
        pose = d_gpose + b*12;
        mean = d_mean1 + b*3;
        out  = d_f1 + b*KK;
    }

    // phase A0: load weights + transform points
    for (int i = tid; i < 8192; i += 256) sm[OFF_W2 + i] = W2g[i];
    if (tid < 192) sm[OFF_W1 + tid] = W1g[tid];
    if (tid < 64)  sm[OFF_B1 + tid] = b1g[tid];
    if (tid < 128) sm[OFF_B2 + tid] = b2g[tid];
    if (tid < 64) {
        int n = blockIdx.x * 64 + tid;
        const float* pp = P + ((size_t)b*NN + n)*3;
        float dx = pp[0] - mean[0], dy = pp[1] - mean[1], dz = pp[2] - mean[2];
        sm[OFF_PTS + tid*3 + 0] = pose[0]*dx + pose[1]*dy + pose[2]*dz  + pose[3];
        sm[OFF_PTS + tid*3 + 1] = pose[4]*dx + pose[5]*dy + pose[6]*dz  + pose[7];
        sm[OFF_PTS + tid*3 + 2] = pose[8]*dx + pose[9]*dy + pose[10]*dz + pose[11];
    }
    __syncthreads();

    // phase A1: h1 = relu(pt @ W1 + b1), 64x64 into sH1 (stride 65)
    for (int idx = tid; idx < 4096; idx += 256) {
        int p = idx >> 6, c1 = idx & 63;
        float x = sm[OFF_PTS + p*3 + 0], y = sm[OFF_PTS + p*3 + 1], z = sm[OFF_PTS + p*3 + 2];
        float v = sm[OFF_B1 + c1];
        v = fmaf(x, sm[OFF_W1 + c1],        v);
        v = fmaf(y, sm[OFF_W1 + 64 + c1],   v);
        v = fmaf(z, sm[OFF_W1 + 128 + c1],  v);
        sm[OFF_H1 + p*65 + c1] = fmaxf(v, 0.f);
    }
    __syncthreads();

    // phase A2: h2 = relu(h1 @ W2 + b2), 64x128 into sH2 (stride 132)
    {
        int p = tid & 63, half = tid >> 6;
        #pragma unroll
        for (int g = 0; g < 8; g++) {
            int c2 = half*32 + g*4;
            float4 acc = *(const float4*)&sm[OFF_B2 + c2];
            #pragma unroll 16
            for (int c1 = 0; c1 < 64; c1++) {
                float h = sm[OFF_H1 + p*65 + c1];
                float4 w = *(const float4*)&sm[OFF_W2 + c1*128 + c2];
                acc.x = fmaf(h, w.x, acc.x);
                acc.y = fmaf(h, w.y, acc.y);
                acc.z = fmaf(h, w.z, acc.z);
                acc.w = fmaf(h, w.w, acc.w);
            }
            acc.x = fmaxf(acc.x, 0.f); acc.y = fmaxf(acc.y, 0.f);
            acc.z = fmaxf(acc.z, 0.f); acc.w = fmaxf(acc.w, 0.f);
            *(float4*)&sm[OFF_H2 + p*132 + c2] = acc;
        }
    }
    __syncthreads();

    // phase B: 16 chunks of 64 output cols; W3 chunk staged in SMEM (aliases W2/H1)
    int kt = tid & 15, pg = tid >> 4, pb = pg * 4;
    for (int kc = 0; kc < 16; kc++) {
        int k0 = kc * 64;
        for (int i = tid; i < 2048; i += 256) {
            int c = i >> 4, kk = (i & 15) * 4;
            *(float4*)&sm[OFF_W3 + c*64 + kk] = *(const float4*)&W3g[(size_t)c*1024 + k0 + kk];
        }
        __syncthreads();

        float4 a0 = {0,0,0,0}, a1 = a0, a2 = a0, a3 = a0;
        const float* h2b = &sm[OFF_H2];
        const float* w3b = &sm[OFF_W3 + kt*4];
        #pragma unroll 8
        for (int c4 = 0; c4 < 32; c4++) {
            float4 wv0 = *(const float4*)&w3b[(c4*4 + 0)*64];
            float4 wv1 = *(const float4*)&w3b[(c4*4 + 1)*64];
            float4 wv2 = *(const float4*)&w3b[(c4*4 + 2)*64];
            float4 wv3 = *(const float4*)&w3b[(c4*4 + 3)*64];
            float4 h;
            h = *(const float4*)&h2b[(pb+0)*132 + c4*4];
            a0.x = fmaf(h.x, wv0.x, a0.x); a0.x = fmaf(h.y, wv1.x, a0.x); a0.x = fmaf(h.z, wv2.x, a0.x); a0.x = fmaf(h.w, wv3.x, a0.x);
            a0.y = fmaf(h.x, wv0.y, a0.y); a0.y = fmaf(h.y, wv1.y, a0.y); a0.y = fmaf(h.z, wv2.y, a0.y); a0.y = fmaf(h.w, wv3.y, a0.y);
            a0.z = fmaf(h.x, wv0.z, a0.z); a0.z = fmaf(h.y, wv1.z, a0.z); a0.z = fmaf(h.z, wv2.z, a0.z); a0.z = fmaf(h.w, wv3.z, a0.z);
            a0.w = fmaf(h.x, wv0.w, a0.w); a0.w = fmaf(h.y, wv1.w, a0.w); a0.w = fmaf(h.z, wv2.w, a0.w); a0.w = fmaf(h.w, wv3.w, a0.w);
            h = *(const float4*)&h2b[(pb+1)*132 + c4*4];
            a1.x = fmaf(h.x, wv0.x, a1.x); a1.x = fmaf(h.y, wv1.x, a1.x); a1.x = fmaf(h.z, wv2.x, a1.x); a1.x = fmaf(h.w, wv3.x, a1.x);
            a1.y = fmaf(h.x, wv0.y, a1.y); a1.y = fmaf(h.y, wv1.y, a1.y); a1.y = fmaf(h.z, wv2.y, a1.y); a1.y = fmaf(h.w, wv3.y, a1.y);
            a1.z = fmaf(h.x, wv0.z, a1.z); a1.z = fmaf(h.y, wv1.z, a1.z); a1.z = fmaf(h.z, wv2.z, a1.z); a1.z = fmaf(h.w, wv3.z, a1.z);
            a1.w = fmaf(h.x, wv0.w, a1.w); a1.w = fmaf(h.y, wv1.w, a1.w); a1.w = fmaf(h.z, wv2.w, a1.w); a1.w = fmaf(h.w, wv3.w, a1.w);
            h = *(const float4*)&h2b[(pb+2)*132 + c4*4];
            a2.x = fmaf(h.x, wv0.x, a2.x); a2.x = fmaf(h.y, wv1.x, a2.x); a2.x = fmaf(h.z, wv2.x, a2.x); a2.x = fmaf(h.w, wv3.x, a2.x);
            a2.y = fmaf(h.x, wv0.y, a2.y); a2.y = fmaf(h.y, wv1.y, a2.y); a2.y = fmaf(h.z, wv2.y, a2.y); a2.y = fmaf(h.w, wv3.y, a2.y);
            a2.z = fmaf(h.x, wv0.z, a2.z); a2.z = fmaf(h.y, wv1.z, a2.z); a2.z = fmaf(h.z, wv2.z, a2.z); a2.z = fmaf(h.w, wv3.z, a2.z);
            a2.w = fmaf(h.x, wv0.w, a2.w); a2.w = fmaf(h.y, wv1.w, a2.w); a2.w = fmaf(h.z, wv2.w, a2.w); a2.w = fmaf(h.w, wv3.w, a2.w);
            h = *(const float4*)&h2b[(pb+3)*132 + c4*4];
            a3.x = fmaf(h.x, wv0.x, a3.x); a3.x = fmaf(h.y, wv1.x, a3.x); a3.x = fmaf(h.z, wv2.x, a3.x); a3.x = fmaf(h.w, wv3.x, a3.x);
            a3.y = fmaf(h.x, wv0.y, a3.y); a3.y = fmaf(h.y, wv1.y, a3.y); a3.y = fmaf(h.z, wv2.y, a3.y); a3.y = fmaf(h.w, wv3.y, a3.y);
            a3.z = fmaf(h.x, wv0.z, a3.z); a3.z = fmaf(h.y, wv1.z, a3.z); a3.z = fmaf(h.z, wv2.z, a3.z); a3.z = fmaf(h.w, wv3.z, a3.z);
            a3.w = fmaf(h.x, wv0.w, a3.w); a3.w = fmaf(h.y, wv1.w, a3.w); a3.w = fmaf(h.z, wv2.w, a3.w); a3.w = fmaf(h.w, wv3.w, a3.w);
        }
        // max over this thread's 4 points
        sm[OFF_RED + pg*64 + kt*4 + 0] = fmaxf(fmaxf(a0.x, a1.x), fmaxf(a2.x, a3.x));
        sm[OFF_RED + pg*64 + kt*4 + 1] = fmaxf(fmaxf(a0.y, a1.y), fmaxf(a2.y, a3.y));
        sm[OFF_RED + pg*64 + kt*4 + 2] = fmaxf(fmaxf(a0.z, a1.z), fmaxf(a2.z, a3.z));
        sm[OFF_RED + pg*64 + kt*4 + 3] = fmaxf(fmaxf(a0.w, a1.w), fmaxf(a2.w, a3.w));
        __syncthreads();
        if (tid < 64) {
            float v = sm[OFF_RED + tid];
            #pragma unroll
            for (int g2 = 1; g2 < 16; g2++) v = fmaxf(v, sm[OFF_RED + g2*64 + tid]);
            v += __ldg(&b3g[k0 + tid]);
            atomicMaxF(&out[k0 + tid], v);
        }
        __syncthreads();
    }
}

// ---------------- J and Hinv ----------------
__global__ void jh_kernel(const float* __restrict__ dt) {
    int b = blockIdx.x, tid = threadIdx.x;
    float dtv[6];
    #pragma unroll
    for (int j = 0; j < 6; j++) dtv[j] = __ldg(&dt[j]);
    double hacc[21];
    #pragma unroll
    for (int q = 0; q < 21; q++) hacc[q] = 0.0;
    for (int k = tid; k < KK; k += 256) {
        float f0k = d_f0[b*KK + k];
        float jv[6];
        #pragma unroll
        for (int j = 0; j < 6; j++) {
            jv[j] = (f0k - d_fj[((size_t)b*6 + j)*KK + k]) / dtv[j];
            d_J[((size_t)b*KK + k)*6 + j] = jv[j];
        }
        int q = 0;
        #pragma unroll
        for (int i = 0; i < 6; i++)
            #pragma unroll
            for (int j = i; j < 6; j++)
                hacc[q++] += (double)jv[i] * (double)jv[j];
    }
    for (int off = 16; off; off >>= 1)
        #pragma unroll
        for (int q = 0; q < 21; q++) hacc[q] += __shfl_down_sync(0xffffffffu, hacc[q], off);
    __shared__ double shH[8][21];
    int lane = tid & 31, w = tid >> 5;
    if (lane == 0) { for (int q = 0; q < 21; q++) shH[w][q] = hacc[q]; }
    __syncthreads();
    if (tid == 0) {
        double s[21];
        for (int q = 0; q < 21; q++) { s[q] = 0.0; for (int w2 = 0; w2 < 8; w2++) s[q] += shH[w2][q]; }
        double H[6][6];
        int q = 0;
        for (int i = 0; i < 6; i++)
            for (int j = i; j < 6; j++) { H[i][j] = s[q]; H[j][i] = s[q]; q++; }
        // Gauss-Jordan with partial pivoting
        double M[6][12];
        for (int i = 0; i < 6; i++)
            for (int j = 0; j < 12; j++) M[i][j] = (j < 6) ? H[i][j] : ((j - 6 == i) ? 1.0 : 0.0);
        for (int col = 0; col < 6; col++) {
            int piv = col; double best = fabs(M[col][col]);
            for (int r2 = col + 1; r2 < 6; r2++)
                if (fabs(M[r2][col]) > best) { best = fabs(M[r2][col]); piv = r2; }
            if (piv != col)
                for (int j = 0; j < 12; j++) { double t = M[col][j]; M[col][j] = M[piv][j]; M[piv][j] = t; }
            double inv = 1.0 / M[col][col];
            for (int j = 0; j < 12; j++) M[col][j] *= inv;
            for (int r2 = 0; r2 < 6; r2++) {
                if (r2 == col) continue;
                double f = M[r2][col];
                for (int j = 0; j < 12; j++) M[r2][j] -= f * M[col][j];
            }
        }
        for (int i = 0; i < 6; i++)
            for (int j = 0; j < 6; j++) d_Hinv[b*36 + i*6 + j] = (float)M[i][6 + j];
    }
}

// ---------------- Gauss-Newton update ----------------
__global__ void update_kernel() {
    int b = blockIdx.x, tid = threadIdx.x;
    double u[6] = {0,0,0,0,0,0};
    for (int k = tid; k < KK; k += 256) {
        float r = d_f1[b*KK + k] - d_f0[b*KK + k];
        d_r[b*KK + k] = r;
        #pragma unroll
        for (int j = 0; j < 6; j++) u[j] += (double)d_J[((size_t)b*KK + k)*6 + j] * (double)r;
    }
    for (int off = 16; off; off >>= 1)
        #pragma unroll
        for (int j = 0; j < 6; j++) u[j] += __shfl_down_sync(0xffffffffu, u[j], off);
    __shared__ double shU[8][6];
    int lane = tid & 31, w = tid >> 5;
    if (lane == 0) { for (int j = 0; j < 6; j++) shU[w][j] = u[j]; }
    __syncthreads();
    if (tid == 0) {
        double uu[6];
        for (int j = 0; j < 6; j++) { uu[j] = 0.0; for (int w2 = 0; w2 < 8; w2++) uu[j] += shU[w2][j]; }
        double dx[6];
        for (int i = 0; i < 6; i++) {
            double s2 = 0.0;
            for (int j = 0; j < 6; j++) s2 += (double)d_Hinv[b*36 + i*6 + j] * uu[j];
            dx[i] = -s2;
        }
        float E[12];
        double wv[3] = {dx[0], dx[1], dx[2]}, vv[3] = {dx[3], dx[4], dx[5]};
        se3_exp_d(wv, vv, E);
        float G[12];
        for (int i = 0; i < 12; i++) G[i] = d_gpose[b*12 + i];
        float Ng[12];
        for (int r2 = 0; r2 < 3; r2++) {
            for (int c = 0; c < 3; c++)
                Ng[r2*4 + c] = E[r2*4+0]*G[0*4+c] + E[r2*4+1]*G[1*4+c] + E[r2*4+2]*G[2*4+c];
            Ng[r2*4 + 3] = E[r2*4+0]*G[3] + E[r2*4+1]*G[7] + E[r2*4+2]*G[11] + E[r2*4+3];
        }
        for (int i = 0; i < 12; i++) d_gpose[b*12 + i] = Ng[i];
    }
}

// ---------------- est_g ----------------
__global__ void estg_kernel() {
    int tid = threadIdx.x;
    if (tid < 8) {
        int b = tid;
        const float* g = d_gpose + b*12;
        const float* m0 = d_mean0 + b*3;
        const float* m1 = d_mean1 + b*3;
        float e[12];
        for (int r = 0; r < 3; r++) {
            e[r*4+0] = g[r*4+0]; e[r*4+1] = g[r*4+1]; e[r*4+2] = g[r*4+2];
            e[r*4+3] = -(g[r*4+0]*m1[0] + g[r*4+1]*m1[1] + g[r*4+2]*m1[2]) + g[r*4+3] + m0[r];
        }
        for (int i = 0; i < 12; i++) d_estg[b*12 + i] = e[i];
    }
}

// ---------------- loss ----------------
__global__ void loss_kernel(const float* __restrict__ p_src) {
    int bi = blockIdx.x;
    int b = bi >> 3, seg = bi & 7;
    int tid = threadIdx.x;
    int n = seg*256 + tid;
    const float* p = p_src + ((size_t)b*NN + n)*3;
    float x = p[0], y = p[1], z = p[2];
    const float* e = d_estg + b*12;
    const float* q = d_igtinv + b*12;
    float s = 0.f;
    #pragma unroll
    for (int r = 0; r < 3; r++) {
        float ae = e[r*4+0]*x + e[r*4+1]*y + e[r*4+2]*z + e[r*4+3];
        float aq = q[r*4+0]*x + q[r*4+1]*y + q[r*4+2]*z + q[r*4+3];
        s += fabsf(ae - aq);
    }
    __shared__ float sr[256];
    sr[tid] = s;
    __syncthreads();
    for (int st = 128; st; st >>= 1) {
        if (tid < st) sr[tid] += sr[tid + st];
        __syncthreads();
    }
    if (tid == 0) d_lpart[bi] = sr[0];
}

// ---------------- output ----------------
__global__ void finish_kernel(float* __restrict__ out, int out_size) {
    int i = blockIdx.x*256 + threadIdx.x;
    if (i < BB*KK && i < out_size) out[i] = d_r[i];
    if (blockIdx.x == 0 && threadIdx.x == 0 && out_size > BB*KK) {
        double s = 0.0;
        for (int j = 0; j < 64; j++) s += (double)d_lpart[j];
        out[BB*KK] = (float)(s / (double)(BB*NN*3));
    }
}

// ---------------- host ----------------
extern "C" void kernel_launch(void* const* d_in, const int* in_sizes, int n_in,
                              void* d_out, int out_size) {
    const float* p_src = (const float*)d_in[0];
    const float* p_tgt = (const float*)d_in[1];
    const float* igt   = (const float*)d_in[2];
    const float* dt    = (const float*)d_in[3];
    const float* W1    = (const float*)d_in[4];
    const float* b1    = (const float*)d_in[5];
    const float* W2    = (const float*)d_in[6];
    const float* b2    = (const float*)d_in[7];
    const float* W3    = (const float*)d_in[8];
    const float* b3    = (const float*)d_in[9];
    float* out = (float*)d_out;

    cudaFuncSetAttribute(encode_kernel<0>, cudaFuncAttributeMaxDynamicSharedMemorySize, SMEM_BYTES);
    cudaFuncSetAttribute(encode_kernel<1>, cudaFuncAttributeMaxDynamicSharedMemorySize, SMEM_BYTES);

    means_kernel<<<BB, 256>>>(p_tgt, p_src);
    setup_kernel<<<1, 32>>>(dt, igt);
    init_f0fj_kernel<<<(BB*KK + BB*6*KK + 255)/256, 256>>>();
    encode_kernel<0><<<dim3(32, BB*7), 256, SMEM_BYTES>>>(p_tgt, W1, b1, W2, b2, W3, b3);
    jh_kernel<<<BB, 256>>>(dt);
    for (int it = 0; it < 5; it++) {
        init_f1_kernel<<<(BB*KK + 255)/256, 256>>>();
        encode_kernel<1><<<dim3(32, BB), 256, SMEM_BYTES>>>(p_src, W1, b1, W2, b2, W3, b3);
        update_kernel<<<BB, 256>>>();
    }
    estg_kernel<<<1, 32>>>();
    loss_kernel<<<64, 256>>>(p_src);
    finish_kernel<<<(BB*KK + 256)/256 + 1, 256>>>(out, out_size);
}